// round 6
// baseline (speedup 1.0000x reference)
#include <cuda_runtime.h>
#include <math.h>

// Problem-shape capacities (this problem: N=16384, E=524288, IN=256, NH=64)
#define MAXN 16384
#define MAXE 524288
#define NHID 64

// ---- scratch (static __device__ arrays; no allocation allowed) ----
__device__ float g_h[(size_t)MAXN * NHID];   // projected features, 4 MB
__device__ int   g_outdeg[MAXN];
__device__ int   g_indeg[MAXN];
__device__ int   g_cursor[MAXN];
__device__ int   g_rowstart[MAXN + 1];
__device__ int   g_esrc[MAXE];
__device__ float g_ealpha[MAXE];

// ---------------------------------------------------------------------------
// 1) zero counters
__global__ void k_zero(int n) {
    int i = blockIdx.x * blockDim.x + threadIdx.x;
    if (i < n) { g_outdeg[i] = 0; g_indeg[i] = 0; g_cursor[i] = 0; }
}

// 2) degree histograms
__global__ void k_degrees(const int* __restrict__ src, const int* __restrict__ dst, int E) {
    int e = blockIdx.x * blockDim.x + threadIdx.x;
    if (e < E) {
        atomicAdd(&g_outdeg[src[e]], 1);
        atomicAdd(&g_indeg[dst[e]], 1);
    }
}

// 3) exclusive prefix scan of indeg -> rowstart (single block, N <= 16384)
__global__ void k_scan(int N, int E) {
    __shared__ int ssum[1024];
    int t = threadIdx.x;
    int items = (N + 1023) >> 10;
    int base = t * items;
    int s = 0;
    for (int i = 0; i < items; i++) {
        int j = base + i;
        if (j < N) s += g_indeg[j];
    }
    ssum[t] = s;
    __syncthreads();
    // Hillis-Steele inclusive scan
    for (int off = 1; off < 1024; off <<= 1) {
        int v = (t >= off) ? ssum[t - off] : 0;
        __syncthreads();
        ssum[t] += v;
        __syncthreads();
    }
    int run = (t == 0) ? 0 : ssum[t - 1];
    for (int i = 0; i < items; i++) {
        int j = base + i;
        if (j < N) { g_rowstart[j] = run; run += g_indeg[j]; }
    }
    if (t == 1023) g_rowstart[N] = E;
}

// 4) scatter edges into CSR-by-dst, with per-edge alpha resolved here
__global__ void k_scatter(const int* __restrict__ src, const int* __restrict__ dst,
                          const int* __restrict__ node_id, const float* __restrict__ alpha,
                          int E, int gene_num) {
    int e = blockIdx.x * blockDim.x + threadIdx.x;
    if (e >= E) return;
    int s = src[e], d = dst[e];
    int sid = node_id[s], did = node_id[d];
    int idx = gene_num + 1;
    if (sid >= 0 && did < 0)       idx = sid;
    else if (did >= 0 && sid < 0)  idx = did;
    else if (sid >= 0 && did >= 0) idx = gene_num;
    float av = alpha[idx];
    int pos = atomicAdd(&g_cursor[d], 1);
    int slot = g_rowstart[d] + pos;
    g_esrc[slot] = s;
    g_ealpha[slot] = av;
}

// 5) h = diag(rsqrt(max(outdeg,1))) * X * W   (M=N, K=IN_FEATS, cols=64)
//    64-row tiles, 256 threads, 4x4 microtile, BK=32
__global__ __launch_bounds__(256) void k_linear(const float* __restrict__ feat,
                                                const float* __restrict__ W,
                                                int N, int K) {
    __shared__ float As[32 * 64];  // [k][r]
    __shared__ float Ws[32 * 64];  // [k][c], row-major chunk copy
    int tid = threadIdx.x;
    int row0 = blockIdx.x * 64;
    int tx = tid & 15, ty = tid >> 4;
    float acc[4][4] = {};
    int lr = tid >> 2;       // 0..63 : row for A load
    int lseg = tid & 3;      // 0..3  : 8 k-values each

    for (int kk = 0; kk < K; kk += 32) {
        const float* fp = feat + (size_t)(row0 + lr) * K + kk + lseg * 8;
        float4 f0 = *(const float4*)fp;
        float4 f1 = *(const float4*)(fp + 4);
        int kb = lseg * 8;
        As[(kb + 0) * 64 + lr] = f0.x; As[(kb + 1) * 64 + lr] = f0.y;
        As[(kb + 2) * 64 + lr] = f0.z; As[(kb + 3) * 64 + lr] = f0.w;
        As[(kb + 4) * 64 + lr] = f1.x; As[(kb + 5) * 64 + lr] = f1.y;
        As[(kb + 6) * 64 + lr] = f1.z; As[(kb + 7) * 64 + lr] = f1.w;
        // W chunk: 32 rows x 64 cols = 2048 floats = 512 float4
        const float4* wp = (const float4*)(W + (size_t)kk * 64);
        ((float4*)Ws)[tid * 2]     = wp[tid * 2];
        ((float4*)Ws)[tid * 2 + 1] = wp[tid * 2 + 1];
        __syncthreads();
        #pragma unroll
        for (int k = 0; k < 32; k++) {
            float4 a = *(const float4*)&As[k * 64 + ty * 4];
            float4 b = *(const float4*)&Ws[k * 64 + tx * 4];
            float ar[4] = {a.x, a.y, a.z, a.w};
            float br[4] = {b.x, b.y, b.z, b.w};
            #pragma unroll
            for (int u = 0; u < 4; u++)
                #pragma unroll
                for (int v = 0; v < 4; v++)
                    acc[u][v] += ar[u] * br[v];
        }
        __syncthreads();
    }
    #pragma unroll
    for (int u = 0; u < 4; u++) {
        int row = row0 + ty * 4 + u;
        float dv = (float)g_outdeg[row];
        if (dv < 1.0f) dv = 1.0f;
        float rs = rsqrtf(dv);
        float* hp = g_h + (size_t)row * NHID + tx * 4;
        hp[0] = acc[u][0] * rs;
        hp[1] = acc[u][1] * rs;
        hp[2] = acc[u][2] * rs;
        hp[3] = acc[u][3] * rs;
    }
}

// 6) aggregate: warp per dst node; lane c handles columns c and c+32.
//    rst[node][:] = (sum_e alpha_e * h[src_e][:]) * rsqrt(max(indeg,1)) + bias
__global__ void k_aggregate(const float* __restrict__ bias, float* __restrict__ rst, int N) {
    int wid = (blockIdx.x * blockDim.x + threadIdx.x) >> 5;
    int lane = threadIdx.x & 31;
    if (wid >= N) return;
    int start = g_rowstart[wid];
    int end = g_rowstart[wid + 1];
    float a0 = 0.0f, a1 = 0.0f;
    #pragma unroll 4
    for (int p = start; p < end; p++) {
        int s = g_esrc[p];
        float av = g_ealpha[p];
        const float* hp = g_h + (size_t)s * NHID;
        a0 += av * hp[lane];
        a1 += av * hp[lane + 32];
    }
    float dv = (float)(end - start);
    if (dv < 1.0f) dv = 1.0f;
    float rs = rsqrtf(dv);
    rst[(size_t)wid * NHID + lane]      = a0 * rs + bias[lane];
    rst[(size_t)wid * NHID + lane + 32] = a1 * rs + bias[lane + 32];
}

// 7) adj = rst * rst^T, exploiting symmetry: only blocks with bj <= bi compute;
//    off-diagonal blocks write both orientations via an smem transpose
//    (stride 129 => conflict-free for row reads AND column reads).
//    128x128 tile, 256 threads, 8x8 microtile, K=64 fully in smem.
__global__ __launch_bounds__(256, 2) void k_gemm_sym(const float* __restrict__ R,
                                                     float* __restrict__ C, int N) {
    int bi = blockIdx.y, bj = blockIdx.x;
    if (bj > bi) return;
    extern __shared__ float sm[];
    float* As = sm;              // [64][128]
    float* Bs = sm + 64 * 128;   // [64][128]
    int tid = threadIdx.x;
    {
        int r = tid >> 1, half = tid & 1;
        const float4* Ap = (const float4*)(R + (size_t)(bi * 128 + r) * NHID) + half * 8;
        const float4* Bp = (const float4*)(R + (size_t)(bj * 128 + r) * NHID) + half * 8;
        #pragma unroll
        for (int q = 0; q < 8; q++) {
            float4 va = Ap[q];
            float4 vb = Bp[q];
            int k = half * 32 + q * 4;
            As[(k + 0) * 128 + r] = va.x; As[(k + 1) * 128 + r] = va.y;
            As[(k + 2) * 128 + r] = va.z; As[(k + 3) * 128 + r] = va.w;
            Bs[(k + 0) * 128 + r] = vb.x; Bs[(k + 1) * 128 + r] = vb.y;
            Bs[(k + 2) * 128 + r] = vb.z; Bs[(k + 3) * 128 + r] = vb.w;
        }
    }
    __syncthreads();
    int tx = tid & 15, ty = tid >> 4;
    float acc[8][8];
    #pragma unroll
    for (int u = 0; u < 8; u++)
        #pragma unroll
        for (int v = 0; v < 8; v++)
            acc[u][v] = 0.0f;
    const float* Arow = As + ty * 8;
    const float* Brow = Bs + tx * 8;
    #pragma unroll 8
    for (int k = 0; k < 64; k++) {
        float4 a0 = *(const float4*)(Arow + k * 128);
        float4 a1 = *(const float4*)(Arow + k * 128 + 4);
        float4 b0 = *(const float4*)(Brow + k * 128);
        float4 b1 = *(const float4*)(Brow + k * 128 + 4);
        float a[8] = {a0.x, a0.y, a0.z, a0.w, a1.x, a1.y, a1.z, a1.w};
        float b[8] = {b0.x, b0.y, b0.z, b0.w, b1.x, b1.y, b1.z, b1.w};
        #pragma unroll
        for (int u = 0; u < 8; u++)
            #pragma unroll
            for (int v = 0; v < 8; v++)
                acc[u][v] += a[u] * b[v];
    }
    __syncthreads();
    float* Cs = sm;  // [128][129] (reuses As/Bs space)
    #pragma unroll
    for (int u = 0; u < 8; u++)
        #pragma unroll
        for (int v = 0; v < 8; v++)
            Cs[(ty * 8 + u) * 129 + tx * 8 + v] = acc[u][v];
    __syncthreads();
    // normal orientation: C[bi*128+r][bj*128+c]; lanes sweep c -> coalesced
    #pragma unroll 8
    for (int it = 0; it < 64; it++) {
        int idx = it * 256 + tid;
        int r = idx >> 7;
        int c = idx & 127;
        C[(size_t)(bi * 128 + r) * N + bj * 128 + c] = Cs[r * 129 + c];
    }
    if (bj < bi) {
        // mirrored: C[bj*128+p][bi*128+q] = Cs[q][p]; lanes sweep q ->
        // coalesced global store, stride-129 column read = conflict-free
        #pragma unroll 8
        for (int it = 0; it < 64; it++) {
            int idx = it * 256 + tid;
            int p = idx >> 7;
            int q = idx & 127;
            C[(size_t)(bj * 128 + p) * N + bi * 128 + q] = Cs[q * 129 + p];
        }
    }
}

// ---------------------------------------------------------------------------
extern "C" void kernel_launch(void* const* d_in, const int* in_sizes, int n_in,
                              void* d_out, int out_size) {
    const float* feat    = (const float*)d_in[0];   // [N, IN_FEATS]
    const float* W       = (const float*)d_in[1];   // [IN_FEATS, 64]
    const float* bias    = (const float*)d_in[2];   // [64]
    const float* alpha   = (const float*)d_in[3];   // [gene_num+2]
    const int*   src     = (const int*)d_in[4];     // [E]
    const int*   dst     = (const int*)d_in[5];     // [E]
    const int*   node_id = (const int*)d_in[6];     // [N]

    int N = in_sizes[6];
    int E = in_sizes[4];
    int K = in_sizes[0] / N;           // IN_FEATS
    int gene_num = in_sizes[3] - 2;

    float* out = (float*)d_out;                  // adj [N,N] then rst [N,64]
    float* rst = out + (size_t)N * N;

    k_zero<<<(N + 255) / 256, 256>>>(N);
    k_degrees<<<(E + 255) / 256, 256>>>(src, dst, E);
    k_scan<<<1, 1024>>>(N, E);
    k_scatter<<<(E + 255) / 256, 256>>>(src, dst, node_id, alpha, E, gene_num);
    k_linear<<<N / 64, 256>>>(feat, W, N, K);
    k_aggregate<<<(N * 32 + 255) / 256, 256>>>(bias, rst, N);

    const int smem = 128 * 129 * 4;  // 66048 B (> As+Bs = 65536 B)
    cudaFuncSetAttribute(k_gemm_sym, cudaFuncAttributeMaxDynamicSharedMemorySize, smem);
    dim3 grid(N / 128, N / 128);
    k_gemm_sym<<<grid, 256, smem>>>(rst, out, N);
}